// round 16
// baseline (speedup 1.0000x reference)
#include <cuda_runtime.h>
#include <cuda_fp16.h>
#include <cstdint>

#define BDIM 8192
#define HDIM 1024

// ---------------- scratch (__device__ globals; no allocation) ----------------
__device__ __half g_XH[(size_t)BDIM * 2048];   // [input | hidden] fp16
__device__ __half g_RH[(size_t)BDIM * 1024];   // r * hidden fp16
__device__ __half g_Wrz[(size_t)2048 * 2048];  // rows: [Wr|Wz] gates, cols: [Wi|Wh]
__device__ __half g_Wch[(size_t)1024 * 2048];  // rows: Wh gate,     cols: [Wih|Whh]
__device__ float  g_zb[(size_t)BDIM * 1024];   // z gate fp32
__device__ int    g_flag[64];                  // rz-producer counters per M-block

// ---------------- helpers ----------------
__device__ __forceinline__ uint32_t smem_u32(const void* p) {
    uint32_t a;
    asm("{ .reg .u64 t; cvta.to.shared.u64 t, %1; cvt.u32.u64 %0, t; }"
        : "=r"(a) : "l"(p));
    return a;
}
#define CP16(sa, ga) \
    asm volatile("cp.async.cg.shared.global [%0], [%1], 16;" :: "r"(sa), "l"(ga) : "memory")
#define CP_COMMIT() asm volatile("cp.async.commit_group;" ::: "memory")
#define CP_WAIT1()  asm volatile("cp.async.wait_group 1;" ::: "memory")

__device__ __forceinline__ void ldm_x4(uint32_t* r, uint32_t addr) {
    asm volatile("ldmatrix.sync.aligned.m8n8.x4.shared.b16 {%0,%1,%2,%3}, [%4];"
                 : "=r"(r[0]), "=r"(r[1]), "=r"(r[2]), "=r"(r[3]) : "r"(addr));
}
__device__ __forceinline__ void mma16816(float* d, const uint32_t* a,
                                         uint32_t b0, uint32_t b1) {
    asm volatile(
        "mma.sync.aligned.m16n8k16.row.col.f32.f16.f16.f32 "
        "{%0,%1,%2,%3}, {%4,%5,%6,%7}, {%8,%9}, {%0,%1,%2,%3};"
        : "+f"(d[0]), "+f"(d[1]), "+f"(d[2]), "+f"(d[3])
        : "r"(a[0]), "r"(a[1]), "r"(a[2]), "r"(a[3]), "r"(b0), "r"(b1));
}
__device__ __forceinline__ float sigm(float x) { return 1.0f / (1.0f + __expf(-x)); }

// smem: 128B rows (64 halves), 8-quad XOR swizzle (q ^= row&7), conflict-free
// CTA tile 128(M) x 64(N), chunk K=64
#define A_TILE_B 16384
#define OFF_B  A_TILE_B
#define STAGE_B (A_TILE_B + 8192)            // 24576
#define NSTAGE 3
#define SMEM_BYTES (NSTAGE * STAGE_B)        // 73728

// ---------------- merged convert: acts (z=0,1) + weights (z=2..7) ----------------
__global__ void convert_all(const float* __restrict__ input, const float* __restrict__ hidden,
                            const float* __restrict__ Wir, const float* __restrict__ Whr,
                            const float* __restrict__ Wiz, const float* __restrict__ Whz,
                            const float* __restrict__ Wih, const float* __restrict__ Whh,
                            int t_act4, int t_w4)
{
    const int z = blockIdx.z;
    if (z == 0 && blockIdx.x == 0 && threadIdx.x < 64)
        g_flag[threadIdx.x] = 0;
    int i = blockIdx.x * blockDim.x + threadIdx.x;
    if (z < 2) {
        if (i >= t_act4) return;
        const float* src = z ? hidden : input;
        const int coff = z ? 1024 : 0;
        int e = i * 4;
        int row = e >> 10;
        int col = e & 1023;
        float4 v = *(const float4*)(src + e);
        size_t d = (size_t)row * 2048 + coff + col;
        *(__half2*)(g_XH + d)     = __halves2half2(__float2half(v.x), __float2half(v.y));
        *(__half2*)(g_XH + d + 2) = __halves2half2(__float2half(v.z), __float2half(v.w));
    } else {
        if (i >= t_w4) return;
        const int w = z - 2;
        const float* src = (w == 0) ? Wir : (w == 1) ? Whr : (w == 2) ? Wiz
                         : (w == 3) ? Whz : (w == 4) ? Wih : Whh;
        __half* dst = (w < 4) ? g_Wrz : g_Wch;
        const int roff = (w == 2 || w == 3) ? 1024 : 0;
        const int coff = (w & 1) ? 1024 : 0;
        int e = i * 4;
        int row = e >> 10;
        int col = e & 1023;
        float4 v = *(const float4*)(src + e);
        size_t d = (size_t)(roff + row) * 2048 + coff + col;
        *(__half2*)(dst + d)     = __halves2half2(__float2half(v.x), __float2half(v.y));
        *(__half2*)(dst + d + 2) = __halves2half2(__float2half(v.z), __float2half(v.w));
    }
}

// ---------------- FUSED HMMA GEMM: rz + candidate in one launch ----------------
// bids [0,2048):   mode0 rz tile. bm=(bid>>5)*128, bn=(bid&31)*64.
//                  bn<1024 -> r epilogue (g_RH), else z epilogue (g_zb).
//                  Then fence + atomicAdd(g_flag[mblk]).
// bids [2048,3072): mode1 candidate tile. Spins g_flag[mblk]==32, GEMM A=[in|r*h],
//                  newh epilogue -> outf.
__global__ __launch_bounds__(256, 3)
void gemm_fused(const float* __restrict__ bir, const float* __restrict__ bhr,
                const float* __restrict__ biz, const float* __restrict__ bhz,
                const float* __restrict__ bih, const float* __restrict__ bhh,
                const float* __restrict__ hid, float* __restrict__ outf)
{
    extern __shared__ __half smem[];
    const uint32_t sbase = smem_u32(smem);

    const int tid  = threadIdx.x;
    const int wid  = tid >> 5;
    const int lane = tid & 31;
    const int wm   = wid & 3;      // 4 warp rows (32 rows each)
    const int wn   = wid >> 2;     // 2 warp cols (32 cols each)

    const int bid = blockIdx.x;
    int mode, bm, bn;
    if (bid < 2048) { mode = 0; bm = (bid >> 5) * 128; bn = (bid & 31) * 64; }
    else { int b = bid - 2048; mode = 1; bm = (b >> 4) * 128; bn = (b & 15) * 64; }
    const int mblk = bm >> 7;

    if (mode == 1) {
        if (tid == 0) {
            while (*(volatile int*)&g_flag[mblk] != 32) { }
            __threadfence();
        }
        __syncthreads();
    }

    const __half* Bw = (mode == 0) ? g_Wrz : g_Wch;

    const int arow = tid >> 1;
    const int aqb  = (tid & 1) * 4;
    const int brow = tid >> 2;
    const int bqb  = (tid & 3) * 2;

    const __half* agX = g_XH + (size_t)(bm + arow) * 2048 + aqb * 8;
    const __half* agR = g_RH + (size_t)(bm + arow) * 1024 + aqb * 8;   // mode 1
    const __half* bgB = Bw + (size_t)(bn + brow) * 2048 + bqb * 8;

    float acc[2][4][4];
#pragma unroll
    for (int i = 0; i < 2; i++)
#pragma unroll
        for (int j = 0; j < 4; j++) {
            acc[i][j][0] = 0.f; acc[i][j][1] = 0.f;
            acc[i][j][2] = 0.f; acc[i][j][3] = 0.f;
        }

    const int C = 32;   // K=2048, chunk=64

    uint32_t a_off[4], b_off[2];
#pragma unroll
    for (int q = 0; q < 4; ++q)
        a_off[q] = (uint32_t)arow * 128 + (uint32_t)((aqb + q) ^ (arow & 7)) * 16;
#pragma unroll
    for (int q = 0; q < 2; ++q)
        b_off[q] = (uint32_t)brow * 128 + (uint32_t)((bqb + q) ^ (brow & 7)) * 16;

    auto load_chunk = [&](int c, int s) {
        const int kk = c << 6;
        const __half* ag = (mode == 1 && kk >= 1024) ? (agR + (kk - 1024)) : (agX + kk);
        const __half* bg = bgB + kk;
        const uint32_t st = sbase + (uint32_t)s * STAGE_B;
#pragma unroll
        for (int q = 0; q < 4; ++q) CP16(st + a_off[q], ag + q * 8);
#pragma unroll
        for (int q = 0; q < 2; ++q) CP16(st + OFF_B + b_off[q], bg + q * 8);
    };

    load_chunk(0, 0); CP_COMMIT();
    load_chunk(1, 1); CP_COMMIT();

    const int a_lrow = lane & 15;
    const int a_q    = lane >> 4;
    const int b_nrow = ((lane >> 4) << 3) + (lane & 7);
    const int b_q    = (lane >> 3) & 1;

    uint32_t a_adr[4][2], b_adr[4][2];
#pragma unroll
    for (int mi = 0; mi < 2; ++mi) {
        int r = wm * 32 + mi * 16 + a_lrow;
        uint32_t roff = (uint32_t)r * 128, rsw = (uint32_t)(r & 7);
#pragma unroll
        for (int ks = 0; ks < 4; ++ks)
            a_adr[ks][mi] = roff + ((uint32_t)(ks * 2 + a_q) ^ rsw) * 16;
    }
#pragma unroll
    for (int j = 0; j < 2; ++j) {
        int r = wn * 32 + j * 16 + b_nrow;
        uint32_t roff = (uint32_t)r * 128, rsw = (uint32_t)(r & 7);
#pragma unroll
        for (int ks = 0; ks < 4; ++ks)
            b_adr[ks][j] = roff + ((uint32_t)(ks * 2 + b_q) ^ rsw) * 16;
    }

    int sc = 0, sl = 2;
    for (int c = 0; c < C; ++c) {
        CP_WAIT1();
        __syncthreads();
        if (c + 2 < C) { load_chunk(c + 2, sl); CP_COMMIT(); }

        const uint32_t aBb = sbase + (uint32_t)sc * STAGE_B;
        const uint32_t bBb = aBb + OFF_B;

#pragma unroll
        for (int ks = 0; ks < 4; ++ks) {
            uint32_t bf[4][2];
#pragma unroll
            for (int j = 0; j < 2; ++j) {
                uint32_t r[4];
                ldm_x4(r, bBb + b_adr[ks][j]);
                bf[j * 2 + 0][0] = r[0]; bf[j * 2 + 0][1] = r[1];
                bf[j * 2 + 1][0] = r[2]; bf[j * 2 + 1][1] = r[3];
            }
            uint32_t ah[2][4];
#pragma unroll
            for (int mi = 0; mi < 2; ++mi)
                ldm_x4(ah[mi], aBb + a_adr[ks][mi]);
#pragma unroll
            for (int mi = 0; mi < 2; ++mi)
#pragma unroll
                for (int ni = 0; ni < 4; ++ni)
                    mma16816(acc[mi][ni], ah[mi], bf[ni][0], bf[ni][1]);
        }
        ++sc; if (sc == 3) sc = 0;
        ++sl; if (sl == 3) sl = 0;
    }

    // ---------------- epilogue ----------------
    const int r_lane = lane >> 2;
    const int c_lane = (lane & 3) * 2;
    const bool is_r = (mode == 0) && (bn < 1024);

    const float* bi0 = (mode == 1) ? bih : (is_r ? bir : biz);
    const float* bh0 = (mode == 1) ? bhh : (is_r ? bhr : bhz);

#pragma unroll
    for (int mi = 0; mi < 2; ++mi) {
        const int r0 = bm + wm * 32 + mi * 16 + r_lane;
#pragma unroll
        for (int ni = 0; ni < 4; ++ni) {
            const int n_ = bn + wn * 32 + ni * 8 + c_lane;
            const int gn = (mode == 0 && n_ >= 1024) ? n_ - 1024 : n_;
            const float bs0 = bi0[gn] + bh0[gn];
            const float bs1 = bi0[gn + 1] + bh0[gn + 1];
#pragma unroll
            for (int h = 0; h < 2; ++h) {
                const int rr = r0 + h * 8;
                const size_t idx = (size_t)rr * HDIM + gn;
                float v0 = acc[mi][ni][h * 2 + 0] + bs0;
                float v1 = acc[mi][ni][h * 2 + 1] + bs1;
                if (mode == 0) {
                    if (is_r) {
                        float2 hv = *(const float2*)(hid + idx);
                        float rv0 = hv.x * sigm(v0);
                        float rv1 = hv.y * sigm(v1);
                        *(__half2*)(g_RH + idx) =
                            __halves2half2(__float2half(rv0), __float2half(rv1));
                    } else {
                        *(float2*)(g_zb + idx) = make_float2(sigm(v0), sigm(v1));
                    }
                } else {
                    float2 zv = *(const float2*)(g_zb + idx);
                    float2 hv = *(const float2*)(hid + idx);
                    float t0 = tanhf(v0), t1 = tanhf(v1);
                    float2 o;
                    o.x = zv.x * hv.x + (1.0f - zv.x) * t0;
                    o.y = zv.y * hv.y + (1.0f - zv.y) * t1;
                    *(float2*)(outf + idx) = o;
                }
            }
        }
    }

    if (mode == 0) {
        __threadfence();
        __syncthreads();
        if (tid == 0) atomicAdd(&g_flag[mblk], 1);
    }
}

// ---------------- warp-per-row log-softmax (no smem, no block barriers) ----------------
__global__ __launch_bounds__(256)
void logsoftmax_warp(const float* __restrict__ nh, float* __restrict__ out)
{
    const int wid  = threadIdx.x >> 5;
    const int lane = threadIdx.x & 31;
    const int row  = blockIdx.x * 8 + wid;

    const float* src = nh + (size_t)row * HDIM;
    float4 v[8];
#pragma unroll
    for (int i = 0; i < 8; ++i)
        v[i] = *(const float4*)(src + (i * 32 + lane) * 4);

    float m = -1e30f;
#pragma unroll
    for (int i = 0; i < 8; ++i)
        m = fmaxf(m, fmaxf(fmaxf(v[i].x, v[i].y), fmaxf(v[i].z, v[i].w)));
#pragma unroll
    for (int s = 16; s >= 1; s >>= 1)
        m = fmaxf(m, __shfl_xor_sync(0xFFFFFFFFu, m, s));

    float sum = 0.f;
#pragma unroll
    for (int i = 0; i < 8; ++i)
        sum += expf(v[i].x - m) + expf(v[i].y - m)
             + expf(v[i].z - m) + expf(v[i].w - m);
#pragma unroll
    for (int s = 16; s >= 1; s >>= 1)
        sum += __shfl_xor_sync(0xFFFFFFFFu, sum, s);

    const float lse = m + logf(sum);
    float* dst = out + (size_t)row * HDIM;
#pragma unroll
    for (int i = 0; i < 8; ++i) {
        float4 o = make_float4(v[i].x - lse, v[i].y - lse,
                               v[i].z - lse, v[i].w - lse);
        *(float4*)(dst + (i * 32 + lane) * 4) = o;
    }
}

// ---------------- launch ----------------
extern "C" void kernel_launch(void* const* d_in, const int* in_sizes, int n_in,
                              void* d_out, int out_size)
{
    const float* input  = (const float*)d_in[0];
    const float* hidden = (const float*)d_in[1];
    const float* Wir = (const float*)d_in[2];
    const float* bir = (const float*)d_in[3];
    const float* Whr = (const float*)d_in[4];
    const float* bhr = (const float*)d_in[5];
    const float* Wiz = (const float*)d_in[6];
    const float* biz = (const float*)d_in[7];
    const float* Whz = (const float*)d_in[8];
    const float* bhz = (const float*)d_in[9];
    const float* Wih = (const float*)d_in[10];
    const float* bih = (const float*)d_in[11];
    const float* Whh = (const float*)d_in[12];
    const float* bhh = (const float*)d_in[13];

    float* out  = (float*)d_out;
    float* newh = out + (size_t)BDIM * HDIM;

    cudaFuncSetAttribute(gemm_fused, cudaFuncAttributeMaxDynamicSharedMemorySize, SMEM_BYTES);

    const int T_ACT = BDIM * 1024 / 4;
    const int T_W = 1024 * 1024 / 4;
    {
        dim3 gc((T_ACT + 255) / 256, 1, 8);  // z=0,1 acts; z=2..7 weights (guarded)
        convert_all<<<gc, 256>>>(input, hidden, Wir, Whr, Wiz, Whz, Wih, Whh,
                                 T_ACT, T_W);
    }

    // fused rz + candidate GEMM: 2048 + 1024 CTAs, M-block dependency flags
    gemm_fused<<<3072, 256, SMEM_BYTES>>>(bir, bhr, biz, bhz, bih, bhh, hidden, newh);

    // warp-per-row log-softmax
    logsoftmax_warp<<<BDIM / 8, 256>>>(newh, out);
}

// round 17
// speedup vs baseline: 1.0577x; 1.0577x over previous
#include <cuda_runtime.h>
#include <cuda_fp16.h>
#include <cstdint>

#define BDIM 8192
#define HDIM 1024

// ---------------- scratch (__device__ globals; no allocation) ----------------
__device__ __half g_XH[(size_t)BDIM * 2048];   // [input | hidden] fp16
__device__ __half g_RH[(size_t)BDIM * 1024];   // r * hidden fp16
__device__ __half g_Wrz[(size_t)2048 * 2048];  // rows: [Wr|Wz] gates, cols: [Wi|Wh]
__device__ __half g_Wch[(size_t)1024 * 2048];  // rows: Wh gate,     cols: [Wih|Whh]
__device__ float  g_zb[(size_t)BDIM * 1024];   // z gate fp32
__device__ int    g_flag[64];                  // rz-producer counters per M-block

// ---------------- helpers ----------------
__device__ __forceinline__ uint32_t smem_u32(const void* p) {
    uint32_t a;
    asm("{ .reg .u64 t; cvta.to.shared.u64 t, %1; cvt.u32.u64 %0, t; }"
        : "=r"(a) : "l"(p));
    return a;
}
#define CP16(sa, ga) \
    asm volatile("cp.async.cg.shared.global [%0], [%1], 16;" :: "r"(sa), "l"(ga) : "memory")
#define CP_COMMIT() asm volatile("cp.async.commit_group;" ::: "memory")
#define CP_WAIT1()  asm volatile("cp.async.wait_group 1;" ::: "memory")

__device__ __forceinline__ void ldm_x4(uint32_t* r, uint32_t addr) {
    asm volatile("ldmatrix.sync.aligned.m8n8.x4.shared.b16 {%0,%1,%2,%3}, [%4];"
                 : "=r"(r[0]), "=r"(r[1]), "=r"(r[2]), "=r"(r[3]) : "r"(addr));
}
__device__ __forceinline__ void mma16816(float* d, const uint32_t* a,
                                         uint32_t b0, uint32_t b1) {
    asm volatile(
        "mma.sync.aligned.m16n8k16.row.col.f32.f16.f16.f32 "
        "{%0,%1,%2,%3}, {%4,%5,%6,%7}, {%8,%9}, {%0,%1,%2,%3};"
        : "+f"(d[0]), "+f"(d[1]), "+f"(d[2]), "+f"(d[3])
        : "r"(a[0]), "r"(a[1]), "r"(a[2]), "r"(a[3]), "r"(b0), "r"(b1));
}
__device__ __forceinline__ float sigm(float x) { return 1.0f / (1.0f + __expf(-x)); }

// smem: 128B rows (64 halves), 8-quad XOR swizzle (q ^= row&7), conflict-free
// CTA tile 128(M) x 64(N), chunk K=64
#define A_TILE_B 16384
#define OFF_B  A_TILE_B
#define STAGE_B (A_TILE_B + 8192)            // 24576
#define NSTAGE 3
#define SMEM_BYTES (NSTAGE * STAGE_B)        // 73728

// ---------------- convert: exact-sized 1D grid, 8 elems/thread ----------------
// bids [0,8192):    acts. src = (bid>>12) ? hidden : input (4096 CTAs each).
// bids [8192,11264): weights (512 CTAs per matrix, 6 matrices).
__global__ __launch_bounds__(256)
void convert_all(const float* __restrict__ input, const float* __restrict__ hidden,
                 const float* __restrict__ Wir, const float* __restrict__ Whr,
                 const float* __restrict__ Wiz, const float* __restrict__ Whz,
                 const float* __restrict__ Wih, const float* __restrict__ Whh,
                 int dummy)
{
    const int bid = blockIdx.x;
    const int tid = threadIdx.x;
    if (bid == 0 && tid < 64) g_flag[tid] = 0;

    const float* src;
    __half* dst;
    int e, coff, roff;
    if (bid < 8192) {
        const int z = bid >> 12;                    // 0 or 1
        const int i = (bid & 4095) * 256 + tid;     // group of 8 elems
        e = i * 8;
        src = z ? hidden : input;
        dst = g_XH;
        coff = z ? 1024 : 0;
        roff = 0;
    } else {
        const int b = bid - 8192;
        const int w = b >> 9;                       // 0..5
        const int i = (b & 511) * 256 + tid;
        e = i * 8;
        src = (w == 0) ? Wir : (w == 1) ? Whr : (w == 2) ? Wiz
            : (w == 3) ? Whz : (w == 4) ? Wih : Whh;
        dst = (w < 4) ? g_Wrz : g_Wch;
        roff = (w == 2 || w == 3) ? 1024 : 0;
        coff = (w & 1) ? 1024 : 0;
    }

    const int row = e >> 10;
    const int col = e & 1023;
    float4 v0 = *(const float4*)(src + e);
    float4 v1 = *(const float4*)(src + e + 4);

    __half2 p0 = __halves2half2(__float2half(v0.x), __float2half(v0.y));
    __half2 p1 = __halves2half2(__float2half(v0.z), __float2half(v0.w));
    __half2 p2 = __halves2half2(__float2half(v1.x), __float2half(v1.y));
    __half2 p3 = __halves2half2(__float2half(v1.z), __float2half(v1.w));
    uint4 o;
    o.x = *(const uint32_t*)&p0;
    o.y = *(const uint32_t*)&p1;
    o.z = *(const uint32_t*)&p2;
    o.w = *(const uint32_t*)&p3;

    const size_t d = (size_t)(roff + row) * 2048 + coff + col;
    *(uint4*)(dst + d) = o;
}

// ---------------- FUSED HMMA GEMM: rz + candidate in one launch ----------------
// bids [0,2048):   mode0 rz tile. bm=(bid>>5)*128, bn=(bid&31)*64.
//                  bn<1024 -> r epilogue (g_RH), else z epilogue (g_zb).
//                  Then fence + atomicAdd(g_flag[mblk]).
// bids [2048,3072): mode1 candidate tile. Spins g_flag[mblk]==32, GEMM A=[in|r*h],
//                  newh epilogue -> outf.
__global__ __launch_bounds__(256, 3)
void gemm_fused(const float* __restrict__ bir, const float* __restrict__ bhr,
                const float* __restrict__ biz, const float* __restrict__ bhz,
                const float* __restrict__ bih, const float* __restrict__ bhh,
                const float* __restrict__ hid, float* __restrict__ outf)
{
    extern __shared__ __half smem[];
    const uint32_t sbase = smem_u32(smem);

    const int tid  = threadIdx.x;
    const int wid  = tid >> 5;
    const int lane = tid & 31;
    const int wm   = wid & 3;      // 4 warp rows (32 rows each)
    const int wn   = wid >> 2;     // 2 warp cols (32 cols each)

    const int bid = blockIdx.x;
    int mode, bm, bn;
    if (bid < 2048) { mode = 0; bm = (bid >> 5) * 128; bn = (bid & 31) * 64; }
    else { int b = bid - 2048; mode = 1; bm = (b >> 4) * 128; bn = (b & 15) * 64; }
    const int mblk = bm >> 7;

    if (mode == 1) {
        if (tid == 0) {
            while (*(volatile int*)&g_flag[mblk] != 32) { }
            __threadfence();
        }
        __syncthreads();
    }

    const __half* Bw = (mode == 0) ? g_Wrz : g_Wch;

    const int arow = tid >> 1;
    const int aqb  = (tid & 1) * 4;
    const int brow = tid >> 2;
    const int bqb  = (tid & 3) * 2;

    const __half* agX = g_XH + (size_t)(bm + arow) * 2048 + aqb * 8;
    const __half* agR = g_RH + (size_t)(bm + arow) * 1024 + aqb * 8;   // mode 1
    const __half* bgB = Bw + (size_t)(bn + brow) * 2048 + bqb * 8;

    float acc[2][4][4];
#pragma unroll
    for (int i = 0; i < 2; i++)
#pragma unroll
        for (int j = 0; j < 4; j++) {
            acc[i][j][0] = 0.f; acc[i][j][1] = 0.f;
            acc[i][j][2] = 0.f; acc[i][j][3] = 0.f;
        }

    const int C = 32;   // K=2048, chunk=64

    uint32_t a_off[4], b_off[2];
#pragma unroll
    for (int q = 0; q < 4; ++q)
        a_off[q] = (uint32_t)arow * 128 + (uint32_t)((aqb + q) ^ (arow & 7)) * 16;
#pragma unroll
    for (int q = 0; q < 2; ++q)
        b_off[q] = (uint32_t)brow * 128 + (uint32_t)((bqb + q) ^ (brow & 7)) * 16;

    auto load_chunk = [&](int c, int s) {
        const int kk = c << 6;
        const __half* ag = (mode == 1 && kk >= 1024) ? (agR + (kk - 1024)) : (agX + kk);
        const __half* bg = bgB + kk;
        const uint32_t st = sbase + (uint32_t)s * STAGE_B;
#pragma unroll
        for (int q = 0; q < 4; ++q) CP16(st + a_off[q], ag + q * 8);
#pragma unroll
        for (int q = 0; q < 2; ++q) CP16(st + OFF_B + b_off[q], bg + q * 8);
    };

    load_chunk(0, 0); CP_COMMIT();
    load_chunk(1, 1); CP_COMMIT();

    const int a_lrow = lane & 15;
    const int a_q    = lane >> 4;
    const int b_nrow = ((lane >> 4) << 3) + (lane & 7);
    const int b_q    = (lane >> 3) & 1;

    uint32_t a_adr[4][2], b_adr[4][2];
#pragma unroll
    for (int mi = 0; mi < 2; ++mi) {
        int r = wm * 32 + mi * 16 + a_lrow;
        uint32_t roff = (uint32_t)r * 128, rsw = (uint32_t)(r & 7);
#pragma unroll
        for (int ks = 0; ks < 4; ++ks)
            a_adr[ks][mi] = roff + ((uint32_t)(ks * 2 + a_q) ^ rsw) * 16;
    }
#pragma unroll
    for (int j = 0; j < 2; ++j) {
        int r = wn * 32 + j * 16 + b_nrow;
        uint32_t roff = (uint32_t)r * 128, rsw = (uint32_t)(r & 7);
#pragma unroll
        for (int ks = 0; ks < 4; ++ks)
            b_adr[ks][j] = roff + ((uint32_t)(ks * 2 + b_q) ^ rsw) * 16;
    }

    int sc = 0, sl = 2;
    for (int c = 0; c < C; ++c) {
        CP_WAIT1();
        __syncthreads();
        if (c + 2 < C) { load_chunk(c + 2, sl); CP_COMMIT(); }

        const uint32_t aBb = sbase + (uint32_t)sc * STAGE_B;
        const uint32_t bBb = aBb + OFF_B;

#pragma unroll
        for (int ks = 0; ks < 4; ++ks) {
            uint32_t bf[4][2];
#pragma unroll
            for (int j = 0; j < 2; ++j) {
                uint32_t r[4];
                ldm_x4(r, bBb + b_adr[ks][j]);
                bf[j * 2 + 0][0] = r[0]; bf[j * 2 + 0][1] = r[1];
                bf[j * 2 + 1][0] = r[2]; bf[j * 2 + 1][1] = r[3];
            }
            uint32_t ah[2][4];
#pragma unroll
            for (int mi = 0; mi < 2; ++mi)
                ldm_x4(ah[mi], aBb + a_adr[ks][mi]);
#pragma unroll
            for (int mi = 0; mi < 2; ++mi)
#pragma unroll
                for (int ni = 0; ni < 4; ++ni)
                    mma16816(acc[mi][ni], ah[mi], bf[ni][0], bf[ni][1]);
        }
        ++sc; if (sc == 3) sc = 0;
        ++sl; if (sl == 3) sl = 0;
    }

    // ---------------- epilogue ----------------
    const int r_lane = lane >> 2;
    const int c_lane = (lane & 3) * 2;
    const bool is_r = (mode == 0) && (bn < 1024);

    const float* bi0 = (mode == 1) ? bih : (is_r ? bir : biz);
    const float* bh0 = (mode == 1) ? bhh : (is_r ? bhr : bhz);

#pragma unroll
    for (int mi = 0; mi < 2; ++mi) {
        const int r0 = bm + wm * 32 + mi * 16 + r_lane;
#pragma unroll
        for (int ni = 0; ni < 4; ++ni) {
            const int n_ = bn + wn * 32 + ni * 8 + c_lane;
            const int gn = (mode == 0 && n_ >= 1024) ? n_ - 1024 : n_;
            const float bs0 = bi0[gn] + bh0[gn];
            const float bs1 = bi0[gn + 1] + bh0[gn + 1];
#pragma unroll
            for (int h = 0; h < 2; ++h) {
                const int rr = r0 + h * 8;
                const size_t idx = (size_t)rr * HDIM + gn;
                float v0 = acc[mi][ni][h * 2 + 0] + bs0;
                float v1 = acc[mi][ni][h * 2 + 1] + bs1;
                if (mode == 0) {
                    if (is_r) {
                        float2 hv = *(const float2*)(hid + idx);
                        float rv0 = hv.x * sigm(v0);
                        float rv1 = hv.y * sigm(v1);
                        *(__half2*)(g_RH + idx) =
                            __halves2half2(__float2half(rv0), __float2half(rv1));
                    } else {
                        *(float2*)(g_zb + idx) = make_float2(sigm(v0), sigm(v1));
                    }
                } else {
                    float2 zv = *(const float2*)(g_zb + idx);
                    float2 hv = *(const float2*)(hid + idx);
                    float t0 = tanhf(v0), t1 = tanhf(v1);
                    float2 o;
                    o.x = zv.x * hv.x + (1.0f - zv.x) * t0;
                    o.y = zv.y * hv.y + (1.0f - zv.y) * t1;
                    *(float2*)(outf + idx) = o;
                }
            }
        }
    }

    if (mode == 0) {
        __threadfence();
        __syncthreads();
        if (tid == 0) atomicAdd(&g_flag[mblk], 1);
    }
}

// ---------------- warp-per-row log-softmax (no smem, no block barriers) ----------------
__global__ __launch_bounds__(256)
void logsoftmax_warp(const float* __restrict__ nh, float* __restrict__ out)
{
    const int wid  = threadIdx.x >> 5;
    const int lane = threadIdx.x & 31;
    const int row  = blockIdx.x * 8 + wid;

    const float* src = nh + (size_t)row * HDIM;
    float4 v[8];
#pragma unroll
    for (int i = 0; i < 8; ++i)
        v[i] = *(const float4*)(src + (i * 32 + lane) * 4);

    float m = -1e30f;
#pragma unroll
    for (int i = 0; i < 8; ++i)
        m = fmaxf(m, fmaxf(fmaxf(v[i].x, v[i].y), fmaxf(v[i].z, v[i].w)));
#pragma unroll
    for (int s = 16; s >= 1; s >>= 1)
        m = fmaxf(m, __shfl_xor_sync(0xFFFFFFFFu, m, s));

    float sum = 0.f;
#pragma unroll
    for (int i = 0; i < 8; ++i)
        sum += expf(v[i].x - m) + expf(v[i].y - m)
             + expf(v[i].z - m) + expf(v[i].w - m);
#pragma unroll
    for (int s = 16; s >= 1; s >>= 1)
        sum += __shfl_xor_sync(0xFFFFFFFFu, sum, s);

    const float lse = m + logf(sum);
    float* dst = out + (size_t)row * HDIM;
#pragma unroll
    for (int i = 0; i < 8; ++i) {
        float4 o = make_float4(v[i].x - lse, v[i].y - lse,
                               v[i].z - lse, v[i].w - lse);
        *(float4*)(dst + (i * 32 + lane) * 4) = o;
    }
}

// ---------------- launch ----------------
extern "C" void kernel_launch(void* const* d_in, const int* in_sizes, int n_in,
                              void* d_out, int out_size)
{
    const float* input  = (const float*)d_in[0];
    const float* hidden = (const float*)d_in[1];
    const float* Wir = (const float*)d_in[2];
    const float* bir = (const float*)d_in[3];
    const float* Whr = (const float*)d_in[4];
    const float* bhr = (const float*)d_in[5];
    const float* Wiz = (const float*)d_in[6];
    const float* biz = (const float*)d_in[7];
    const float* Whz = (const float*)d_in[8];
    const float* bhz = (const float*)d_in[9];
    const float* Wih = (const float*)d_in[10];
    const float* bih = (const float*)d_in[11];
    const float* Whh = (const float*)d_in[12];
    const float* bhh = (const float*)d_in[13];

    float* out  = (float*)d_out;
    float* newh = out + (size_t)BDIM * HDIM;

    cudaFuncSetAttribute(gemm_fused, cudaFuncAttributeMaxDynamicSharedMemorySize, SMEM_BYTES);

    // exact-sized convert: 8192 act CTAs + 3072 weight CTAs
    convert_all<<<11264, 256>>>(input, hidden, Wir, Whr, Wiz, Whz, Wih, Whh, 0);

    // fused rz + candidate GEMM: 2048 + 1024 CTAs, M-block dependency flags
    gemm_fused<<<3072, 256, SMEM_BYTES>>>(bir, bhr, biz, bhz, bih, bhh, hidden, newh);

    // warp-per-row log-softmax
    logsoftmax_warp<<<BDIM / 8, 256>>>(newh, out);
}